// round 2
// baseline (speedup 1.0000x reference)
#include <cuda_runtime.h>
#include <cuda_bf16.h>
#include <cstdint>

// ----------------------------------------------------------------------------
// Problem constants
// ----------------------------------------------------------------------------
#define NROWS   12544          // 16*28*28 feature rows
#define MROWS   16384          // memory bank rows
#define KDIM    1536           // feature dim (512 + 1024)
#define BATCH   16
#define HW28    784            // 28*28
#define OUTHW   50176          // 224*224

// GEMM tiling (mma.sync fallback, compute_103-legal)
#define BM      128
#define BN      128
#define BK      32
#define NKT     (KDIM / BK)    // 48 k-iterations
#define STAGES  4
#define STAGE_BYTES 16384      // A 8KB + B 8KB
#define SMEM_MSQ_OFF (STAGES * STAGE_BYTES)          // 65536
#define SMEM_TOTAL   (SMEM_MSQ_OFF + BN * 4)         // 66048

// ----------------------------------------------------------------------------
// Device scratch (static globals: no allocation anywhere)
// ----------------------------------------------------------------------------
__device__ __nv_bfloat16 g_feats[(size_t)NROWS * KDIM];   // 38.5 MB
__device__ float         g_xsq[NROWS];
__device__ __nv_bfloat16 g_mb[(size_t)MROWS * KDIM];      // 50.3 MB
__device__ float         g_msq[MROWS];
__device__ unsigned      g_minbits[NROWS];                // min d2 as uint bits

// ----------------------------------------------------------------------------
// Helpers
// ----------------------------------------------------------------------------
__device__ __forceinline__ uint32_t smem_u32(const void* p) {
    uint32_t a;
    asm("{ .reg .u64 t; cvta.to.shared.u64 t, %1; cvt.u32.u64 %0, t; }"
        : "=r"(a) : "l"(p));
    return a;
}
// 64-byte-row XOR swizzle: bits[4:5] ^= bits[7:8] (row bits 1..2)
__device__ __forceinline__ uint32_t swz64(uint32_t off) {
    return off ^ ((off >> 3) & 0x30);
}
__device__ __forceinline__ void cp_async16(uint32_t dst, const void* src) {
    asm volatile("cp.async.cg.shared.global [%0], [%1], 16;\n"
                 :: "r"(dst), "l"(src) : "memory");
}
__device__ __forceinline__ void ldmx4(uint32_t* r, uint32_t addr) {
    asm volatile("ldmatrix.sync.aligned.m8n8.x4.shared.b16 {%0,%1,%2,%3}, [%4];"
                 : "=r"(r[0]), "=r"(r[1]), "=r"(r[2]), "=r"(r[3]) : "r"(addr));
}
__device__ __forceinline__ void mma16816(float* d, const uint32_t* a,
                                         uint32_t b0, uint32_t b1) {
    asm volatile(
        "mma.sync.aligned.m16n8k16.row.col.f32.bf16.bf16.f32 "
        "{%0,%1,%2,%3}, {%4,%5,%6,%7}, {%8,%9}, {%0,%1,%2,%3};"
        : "+f"(d[0]), "+f"(d[1]), "+f"(d[2]), "+f"(d[3])
        : "r"(a[0]), "r"(a[1]), "r"(a[2]), "r"(a[3]), "r"(b0), "r"(b1));
}

// ----------------------------------------------------------------------------
// Kernel 0: reset running-min buffer
// ----------------------------------------------------------------------------
__global__ void init_kernel() {
    int i = blockIdx.x * blockDim.x + threadIdx.x;
    if (i < NROWS) g_minbits[i] = 0x7F7FFFFFu;  // FLT_MAX bits
}

// ----------------------------------------------------------------------------
// Kernel 1: build feats (concat + bilinear upsample 14->28) + x_sq
// One block per output row n = b*784 + h*28 + w. 256 threads over 1536 chans.
// ----------------------------------------------------------------------------
__global__ void prep_kernel(const float* __restrict__ f2, const float* __restrict__ f3) {
    int n = blockIdx.x;
    int b = n / HW28;
    int hw = n - b * HW28;
    int h = hw / 28, w = hw - (hw / 28) * 28;

    // half-pixel bilinear 14->28: src = dst*0.5 - 0.25
    float sy = h * 0.5f - 0.25f;
    float sx = w * 0.5f - 0.25f;
    float fy0 = floorf(sy), fx0 = floorf(sx);
    float wy = sy - fy0, wx = sx - fx0;
    int y0 = (int)fy0, x0 = (int)fx0;
    int y0c = max(0, min(13, y0)),   y1c = max(0, min(13, y0 + 1));
    int x0c = max(0, min(13, x0)),   x1c = max(0, min(13, x0 + 1));

    int tid = threadIdx.x;
    float ssum = 0.f;
    __nv_bfloat16* frow = g_feats + (size_t)n * KDIM;

    #pragma unroll
    for (int cc = 0; cc < 6; cc++) {
        int c = tid + cc * 256;
        float v;
        if (c < 512) {
            v = f2[(((size_t)b * 512 + c) * 28 + h) * 28 + w];
        } else {
            const float* base = f3 + ((size_t)b * 1024 + (c - 512)) * 196;
            float v00 = base[y0c * 14 + x0c];
            float v01 = base[y0c * 14 + x1c];
            float v10 = base[y1c * 14 + x0c];
            float v11 = base[y1c * 14 + x1c];
            v = (1.f - wy) * ((1.f - wx) * v00 + wx * v01)
              +        wy  * ((1.f - wx) * v10 + wx * v11);
        }
        frow[c] = __float2bfloat16(v);
        ssum += v * v;
    }
    __shared__ float sred[256];
    sred[tid] = ssum;
    __syncthreads();
    for (int s = 128; s > 0; s >>= 1) {
        if (tid < s) sred[tid] += sred[tid + s];
        __syncthreads();
    }
    if (tid == 0) g_xsq[n] = sred[0];
}

// ----------------------------------------------------------------------------
// Kernel 2: memory_bank -> bf16 + m_sq. One block per bank row.
// ----------------------------------------------------------------------------
__global__ void mb_kernel(const float* __restrict__ mb) {
    int j = blockIdx.x;
    int tid = threadIdx.x;
    const float* src = mb + (size_t)j * KDIM;
    __nv_bfloat16* dst = g_mb + (size_t)j * KDIM;
    float ssum = 0.f;
    #pragma unroll
    for (int cc = 0; cc < 6; cc++) {
        int c = tid + cc * 256;
        float v = src[c];
        dst[c] = __float2bfloat16(v);
        ssum += v * v;
    }
    __shared__ float sred[256];
    sred[tid] = ssum;
    __syncthreads();
    for (int s = 128; s > 0; s >>= 1) {
        if (tid < s) sred[tid] += sred[tid + s];
        __syncthreads();
    }
    if (tid == 0) g_msq[j] = sred[0];
}

// ----------------------------------------------------------------------------
// Kernel 3: pipelined bf16 mma.sync GEMM with fused row-min epilogue.
// grid (98, 128), 256 threads (8 warps as 2x4). CTA tile 128x128, K pipelined
// over 48 iterations of BK=32 with 4-stage cp.async.
// ----------------------------------------------------------------------------
__global__ void __launch_bounds__(256) gemm_min_fb() {
    extern __shared__ char smem[];
    const int tid = threadIdx.x;
    const int wid = tid >> 5, lane = tid & 31;
    const int row_base = blockIdx.x * BM;
    const int n_base = blockIdx.y * BN;
    float* msq_s = (float*)(smem + SMEM_MSQ_OFF);
    const uint32_t sb = smem_u32(smem);

    for (int i = tid; i < BN; i += 256) msq_s[i] = g_msq[n_base + i];

    // per-lane ldmatrix byte offsets (within a tile), per k-halfstep ks=0/1
    uint32_t a_off[2], b_off[2];
    {
        uint32_t arow = (uint32_t)((lane & 15) * 64 + (lane >> 4) * 16);
        uint32_t brow = (uint32_t)((((lane >> 4) << 3) + (lane & 7)) * 64
                                   + ((lane >> 3) & 1) * 16);
        a_off[0] = swz64(arow);       a_off[1] = swz64(arow + 32);
        b_off[0] = swz64(brow);       b_off[1] = swz64(brow + 32);
    }
    const int mbw = (wid >> 2) * 64;   // warp m base within CTA tile
    const int nbw = (wid & 3) * 32;    // warp n base within CTA tile

    float acc[4][4][4];
    #pragma unroll
    for (int mi = 0; mi < 4; mi++)
        #pragma unroll
        for (int ni = 0; ni < 4; ni++)
            #pragma unroll
            for (int j = 0; j < 4; j++) acc[mi][ni][j] = 0.f;

    // cp.async one pipeline stage: A 128x32 + B 128x32 bf16, 16B chunks
    auto issue_stage = [&](int kt) {
        uint32_t abase = sb + (uint32_t)((kt & (STAGES - 1)) * STAGE_BYTES);
        uint32_t bbase = abase + 8192;
        int kb = kt * BK;
        #pragma unroll
        for (int h = 0; h < 2; h++) {
            int i = tid + h * 256;
            int r = i >> 2, cs = i & 3;
            uint32_t doff = swz64((uint32_t)(r * 64 + cs * 16));
            cp_async16(abase + doff,
                       g_feats + (size_t)(row_base + r) * KDIM + kb + cs * 8);
            cp_async16(bbase + doff,
                       g_mb + (size_t)(n_base + r) * KDIM + kb + cs * 8);
        }
    };

    // prologue: 3 stages in flight
    issue_stage(0); asm volatile("cp.async.commit_group;" ::: "memory");
    issue_stage(1); asm volatile("cp.async.commit_group;" ::: "memory");
    issue_stage(2); asm volatile("cp.async.commit_group;" ::: "memory");

    for (int kt = 0; kt < NKT; kt++) {
        asm volatile("cp.async.wait_group 2;" ::: "memory");
        __syncthreads();

        // keep pipeline full (empty commit keeps group accounting uniform)
        if (kt + 3 < NKT) issue_stage(kt + 3);
        asm volatile("cp.async.commit_group;" ::: "memory");

        uint32_t abase = sb + (uint32_t)((kt & (STAGES - 1)) * STAGE_BYTES);
        uint32_t bbase = abase + 8192;

        #pragma unroll
        for (int ks = 0; ks < 2; ks++) {
            uint32_t ar[4][4], br[2][4];
            #pragma unroll
            for (int mi = 0; mi < 4; mi++)
                ldmx4(ar[mi], abase + (uint32_t)((mbw + mi * 16) * 64) + a_off[ks]);
            #pragma unroll
            for (int nb = 0; nb < 2; nb++)
                ldmx4(br[nb], bbase + (uint32_t)((nbw + nb * 16) * 64) + b_off[ks]);
            #pragma unroll
            for (int mi = 0; mi < 4; mi++)
                #pragma unroll
                for (int ni = 0; ni < 4; ni++)
                    mma16816(acc[mi][ni], ar[mi],
                             br[ni >> 1][(ni & 1) * 2], br[ni >> 1][(ni & 1) * 2 + 1]);
        }
    }

    // epilogue: q = min_n (m_sq[n] - 2*dot); d2 = max(xsq + q, 0); atomicMin
    #pragma unroll
    for (int mi = 0; mi < 4; mi++) {
        float q0 = 3.4e38f, q1 = 3.4e38f;
        #pragma unroll
        for (int ni = 0; ni < 4; ni++) {
            int n = nbw + ni * 8 + (lane & 3) * 2;
            float ms0 = msq_s[n], ms1 = msq_s[n + 1];
            q0 = fminf(q0, fminf(fmaf(-2.f, acc[mi][ni][0], ms0),
                                 fmaf(-2.f, acc[mi][ni][1], ms1)));
            q1 = fminf(q1, fminf(fmaf(-2.f, acc[mi][ni][2], ms0),
                                 fmaf(-2.f, acc[mi][ni][3], ms1)));
        }
        q0 = fminf(q0, __shfl_xor_sync(0xffffffffu, q0, 1));
        q0 = fminf(q0, __shfl_xor_sync(0xffffffffu, q0, 2));
        q1 = fminf(q1, __shfl_xor_sync(0xffffffffu, q1, 1));
        q1 = fminf(q1, __shfl_xor_sync(0xffffffffu, q1, 2));
        if ((lane & 3) == 0) {
            int r0 = row_base + mbw + mi * 16 + (lane >> 2);
            int r1 = r0 + 8;
            float d0 = fmaxf(g_xsq[r0] + q0, 0.f);
            float d1 = fmaxf(g_xsq[r1] + q1, 0.f);
            atomicMin(&g_minbits[r0], __float_as_uint(d0));
            atomicMin(&g_minbits[r1], __float_as_uint(d1));
        }
    }
}

// ----------------------------------------------------------------------------
// Kernel 4: sqrt + bilinear 28->224 + per-batch max. One block per batch.
// Output: [0, 16*50176) anomaly map, [16*50176, +16) pred scores.
// ----------------------------------------------------------------------------
__global__ void finalize_kernel(float* __restrict__ out) {
    int b = blockIdx.x;
    int tid = threadIdx.x;
    __shared__ float s28[HW28];
    __shared__ float sred[256];

    for (int i = tid; i < HW28; i += 256)
        s28[i] = sqrtf(__uint_as_float(g_minbits[b * HW28 + i]));
    __syncthreads();

    float mx = 0.f;
    float* omap = out + (size_t)b * OUTHW;
    for (int p = tid; p < OUTHW; p += 256) {
        int i = p / 224, j = p - (p / 224) * 224;
        float sy = i * 0.125f - 0.4375f;
        float sx = j * 0.125f - 0.4375f;
        float fy0 = floorf(sy), fx0 = floorf(sx);
        float wy = sy - fy0, wx = sx - fx0;
        int y0 = (int)fy0, x0 = (int)fx0;
        int y0c = max(0, min(27, y0)),   y1c = max(0, min(27, y0 + 1));
        int x0c = max(0, min(27, x0)),   x1c = max(0, min(27, x0 + 1));
        float v00 = s28[y0c * 28 + x0c], v01 = s28[y0c * 28 + x1c];
        float v10 = s28[y1c * 28 + x0c], v11 = s28[y1c * 28 + x1c];
        float v = (1.f - wy) * ((1.f - wx) * v00 + wx * v01)
                +        wy  * ((1.f - wx) * v10 + wx * v11);
        omap[p] = v;
        mx = fmaxf(mx, v);
    }
    sred[tid] = mx;
    __syncthreads();
    for (int s = 128; s > 0; s >>= 1) {
        if (tid < s) sred[tid] = fmaxf(sred[tid], sred[tid + s]);
        __syncthreads();
    }
    if (tid == 0) out[(size_t)BATCH * OUTHW + b] = sred[0];
}

// ----------------------------------------------------------------------------
// Launch
// ----------------------------------------------------------------------------
extern "C" void kernel_launch(void* const* d_in, const int* in_sizes, int n_in,
                              void* d_out, int out_size) {
    const float* feat2 = (const float*)d_in[0];
    const float* feat3 = (const float*)d_in[1];
    const float* mbank = (const float*)d_in[2];
    float* out = (float*)d_out;

    cudaFuncSetAttribute(gemm_min_fb,
                         cudaFuncAttributeMaxDynamicSharedMemorySize, SMEM_TOTAL);

    init_kernel<<<(NROWS + 255) / 256, 256>>>();
    prep_kernel<<<NROWS, 256>>>(feat2, feat3);
    mb_kernel<<<MROWS, 256>>>(mbank);
    gemm_min_fb<<<dim3(NROWS / BM, MROWS / BN), 256, SMEM_TOTAL>>>();
    finalize_kernel<<<BATCH, 256>>>(out);
}